// round 15
// baseline (speedup 1.0000x reference)
#include <cuda_runtime.h>
#include <cuda_bf16.h>
#include <math.h>

#define BSZ   2048
#define HID   2048
#define G4    8192
#define OUTD  2048
#define INDIM 2047
#define KDIM  2048
#define KB2   4096          // physical: 2 segments (hi, lo); logical K = 3 segments
#define MAXP  100
#define TSPLIT 12
#define NTHR  256
#define LDA   40            // smem row stride in elements (80B, conflict-free)
#define KCH   32
#define NCHUNK 192          // 3 logical segments x 64 chunks

// ---------------- device scratch ----------------
__device__ __align__(16) __nv_bfloat16 g_xpadb[(size_t)BSZ * KB2];  // [Ah|Al]
__device__ __align__(16) __nv_bfloat16 g_hxb  [(size_t)BSZ * KB2];  // [Ah|Al]
__device__ __align__(16) __nv_bfloat16 g_ahxb [(size_t)BSZ * KB2];  // [Ah|Al]
__device__ __align__(16) __nv_bfloat16 g_wihb [(size_t)G4  * KB2];  // [Bh|Bl]
__device__ __align__(16) __nv_bfloat16 g_whhb [(size_t)G4  * KB2];  // [Bh|Bl]
__device__ __align__(16) __nv_bfloat16 g_wob  [(size_t)OUTD* KB2];  // [Bh|Bl]
__device__ __align__(16) float g_base [(size_t)BSZ * G4];
__device__ __align__(16) float g_gates[(size_t)BSZ * G4];
__device__ __align__(16) float g_hx   [(size_t)BSZ * HID];
__device__ __align__(16) float g_cx   [(size_t)BSZ * HID];
__device__ float g_gxacc[BSZ];
__device__ int   g_halted[BSZ];
__device__ int   g_rowidx[2][BSZ + 128];
__device__ int   g_blkdone[MAXP];
__device__ int   g_nactive;
__device__ int   g_done_step;
__device__ int   g_ponder;
__device__ unsigned g_sync_cnt;
__device__ unsigned g_sync_gen;

__device__ __forceinline__ float sigf(float x) { return 1.0f / (1.0f + expf(-x)); }

__device__ __forceinline__ void split_bf16(float v, __nv_bfloat16& hi, __nv_bfloat16& lo)
{
    hi = __float2bfloat16(v);
    lo = __float2bfloat16(v - __bfloat162float(hi));
}

// ---------------- PTX helpers ----------------
__device__ __forceinline__ unsigned su32(const void* p)
{
    return (unsigned)__cvta_generic_to_shared(p);
}
__device__ __forceinline__ void cp16(unsigned dst, const void* src)
{
    asm volatile("cp.async.cg.shared.global [%0], [%1], 16;" :: "r"(dst), "l"(src));
}
__device__ __forceinline__ void cp_commit()
{
    asm volatile("cp.async.commit_group;" ::: "memory");
}
template <int N> __device__ __forceinline__ void cp_wait()
{
    asm volatile("cp.async.wait_group %0;" :: "n"(N) : "memory");
}
__device__ __forceinline__ void ldsm4(unsigned& r0, unsigned& r1, unsigned& r2, unsigned& r3,
                                      unsigned addr)
{
    asm volatile("ldmatrix.sync.aligned.m8n8.x4.shared.b16 {%0,%1,%2,%3}, [%4];"
                 : "=r"(r0), "=r"(r1), "=r"(r2), "=r"(r3) : "r"(addr));
}
__device__ __forceinline__ void mma16816(float& d0, float& d1, float& d2, float& d3,
                                         unsigned a0, unsigned a1, unsigned a2, unsigned a3,
                                         unsigned b0, unsigned b1)
{
    asm volatile("mma.sync.aligned.m16n8k16.row.col.f32.bf16.bf16.f32 "
                 "{%0,%1,%2,%3}, {%4,%5,%6,%7}, {%8,%9}, {%0,%1,%2,%3};"
                 : "+f"(d0), "+f"(d1), "+f"(d2), "+f"(d3)
                 : "r"(a0), "r"(a1), "r"(a2), "r"(a3), "r"(b0), "r"(b1));
}

// logical chunk -> physical element offset (seg size 2048, 64 chunks/seg)
__device__ __forceinline__ int a_off(int ch)   // segA = {0,0,1}
{
    int seg = ch >> 6, c = ch & 63;
    return ((seg == 2) ? 2048 : 0) + c * KCH;
}
__device__ __forceinline__ int b_off(int ch)   // segB = {0,1,0}
{
    int seg = ch >> 6, c = ch & 63;
    return ((seg == 1) ? 2048 : 0) + c * KCH;
}

// ------------- 128x128 bf16 MMA GEMM tile (R9 config — at mma.sync ceiling) -------------
// 256 threads = 8 warps (2x4). Warp tile 64x32. cp.async double-buffered smem.
// Logical K = 3 segments (Ah·Bh, Ah·Bl, Al·Bh) over 2-segment physical buffers.
__device__ __forceinline__ void mma_gemm(
    const __nv_bfloat16* __restrict__ A, const int* __restrict__ rows,
    const __nv_bfloat16* __restrict__ B,
    int m0, int n0, float (&acc)[4][4][4], int* rowmap)
{
    __shared__ __align__(16) __nv_bfloat16 As[2][128 * LDA];
    __shared__ __align__(16) __nv_bfloat16 Bs[2][128 * LDA];
    const int tid = threadIdx.x;

    if (rows) {
        if (tid < 128) rowmap[tid] = rows[m0 + tid];
        __syncthreads();
    }

    const unsigned suA[2] = { su32(&As[0][0]), su32(&As[1][0]) };
    const unsigned suB[2] = { su32(&Bs[0][0]), su32(&Bs[1][0]) };
    const __nv_bfloat16* srcA[2];
    const __nv_bfloat16* srcB[2];
    unsigned offs[2];
    #pragma unroll
    for (int u = 0; u < 2; u++) {
        int idx = tid * 2 + u;          // 0..511
        int row = idx >> 2, sub = idx & 3;
        int ar  = rows ? rowmap[row] : (m0 + row);
        srcA[u] = A + (size_t)ar * KB2 + sub * 8;
        srcB[u] = B + (size_t)(n0 + row) * KB2 + sub * 8;
        offs[u] = (unsigned)(row * (LDA * 2) + sub * 16);   // bytes
    }

    const int lane = tid & 31, warpid = tid >> 5;
    const int wm = warpid >> 2, wn = warpid & 3;
    const int a_r = lane & 15;
    const int a_c = (lane >> 4) << 3;
    const int b_r = ((lane >> 4) << 3) + (lane & 7);
    const int b_c = ((lane >> 3) & 1) << 3;

    #pragma unroll
    for (int u = 0; u < 2; u++) cp16(suA[0] + offs[u], srcA[u] + a_off(0));
    #pragma unroll
    for (int u = 0; u < 2; u++) cp16(suB[0] + offs[u], srcB[u] + b_off(0));
    cp_commit();

    for (int ch = 0; ch < NCHUNK; ch++) {
        const int buf = ch & 1;
        if (ch + 1 < NCHUNK) {
            const int ao = a_off(ch + 1), bo = b_off(ch + 1);
            const int nb = buf ^ 1;
            #pragma unroll
            for (int u = 0; u < 2; u++) cp16(suA[nb] + offs[u], srcA[u] + ao);
            #pragma unroll
            for (int u = 0; u < 2; u++) cp16(suB[nb] + offs[u], srcB[u] + bo);
            cp_commit();
            cp_wait<1>();
        } else {
            cp_wait<0>();
        }
        __syncthreads();

        #pragma unroll
        for (int kh = 0; kh < 2; kh++) {
            const int kb = kh * 16;
            unsigned af[4][4], bq[2][4];
            #pragma unroll
            for (int mi = 0; mi < 4; mi++) {
                int r = wm * 64 + mi * 16 + a_r;
                ldsm4(af[mi][0], af[mi][1], af[mi][2], af[mi][3],
                      suA[buf] + (unsigned)(r * (LDA * 2) + (kb + a_c) * 2));
            }
            #pragma unroll
            for (int np = 0; np < 2; np++) {
                int r = wn * 32 + np * 16 + b_r;
                ldsm4(bq[np][0], bq[np][1], bq[np][2], bq[np][3],
                      suB[buf] + (unsigned)(r * (LDA * 2) + (kb + b_c) * 2));
            }
            #pragma unroll
            for (int mi = 0; mi < 4; mi++) {
                #pragma unroll
                for (int np = 0; np < 2; np++) {
                    mma16816(acc[mi][np*2][0], acc[mi][np*2][1], acc[mi][np*2][2], acc[mi][np*2][3],
                             af[mi][0], af[mi][1], af[mi][2], af[mi][3],
                             bq[np][0], bq[np][1]);
                    mma16816(acc[mi][np*2+1][0], acc[mi][np*2+1][1], acc[mi][np*2+1][2], acc[mi][np*2+1][3],
                             af[mi][0], af[mi][1], af[mi][2], af[mi][3],
                             bq[np][2], bq[np][3]);
                }
            }
        }
        __syncthreads();
    }
}

// ---------------- fused setup: all init/pack/convert work in ONE kernel ----------------
__global__ void __launch_bounds__(NTHR)
k_setup(const float* __restrict__ x,
        const float* __restrict__ hx0, const float* __restrict__ cx0,
        const float* __restrict__ W_ih, const float* __restrict__ W_hh,
        const float* __restrict__ W_o, float* __restrict__ out)
{
    const size_t nA = (size_t)2 * BSZ * HID / 4;
    const size_t nB = (size_t)BSZ * HID / 4;
    const size_t nC = (size_t)BSZ * (KDIM / 4);
    const size_t nD = (size_t)G4  * (KDIM / 4);
    const size_t nE = (size_t)G4  * (KDIM / 4);
    const size_t nF = (size_t)OUTD* (KDIM / 4);
    const size_t nG = BSZ + 128;
    const size_t e0 = nA, e1 = e0 + nB, e2 = e1 + nC, e3 = e2 + nD,
                 e4 = e3 + nE, e5 = e4 + nF, e6 = e5 + nG;

    size_t i      = (size_t)blockIdx.x * blockDim.x + threadIdx.x;
    size_t stride = (size_t)gridDim.x * blockDim.x;
    for (size_t k = i; k < e6; k += stride) {
        if (k < e0) {
            float4 z = {0.f, 0.f, 0.f, 0.f};
            *(float4*)(out + k * 4) = z;
        } else if (k < e1) {                            // hx/cx + hxb
            size_t j = k - e0;
            size_t row = j >> 9, c4 = (j & 511) * 4;
            size_t off = row * HID + c4;
            float4 h = *(const float4*)(hx0 + off);
            float4 c = *(const float4*)(cx0 + off);
            *(float4*)(g_hx + off) = h;
            *(float4*)(g_cx + off) = c;
            __nv_bfloat16 hi[4], lo[4];
            split_bf16(h.x, hi[0], lo[0]);
            split_bf16(h.y, hi[1], lo[1]);
            split_bf16(h.z, hi[2], lo[2]);
            split_bf16(h.w, hi[3], lo[3]);
            __nv_bfloat16* dst = g_hxb + row * KB2 + c4;
            *(uint2*)(dst)        = *(uint2*)hi;
            *(uint2*)(dst + 2048) = *(uint2*)lo;
        } else if (k < e2) {                            // xpad
            size_t j = k - e1;
            size_t row = j >> 9, c0 = (j & 511) * 4;
            const float* xr = x + row * INDIM;
            __nv_bfloat16 hi[4], lo[4];
            #pragma unroll
            for (int u = 0; u < 4; u++) {
                size_t col = c0 + u;
                float v = (col < INDIM) ? xr[col] : 0.f;
                split_bf16(v, hi[u], lo[u]);
            }
            __nv_bfloat16* dst = g_xpadb + row * KB2 + c0;
            *(uint2*)(dst)        = *(uint2*)hi;
            *(uint2*)(dst + 2048) = *(uint2*)lo;
        } else if (k < e5) {                            // weight conversions
            size_t j;
            const float* W;
            __nv_bfloat16* Wb;
            if (k < e3)      { j = k - e2; W = W_ih; Wb = g_wihb; }
            else if (k < e4) { j = k - e3; W = W_hh; Wb = g_whhb; }
            else             { j = k - e4; W = W_o;  Wb = g_wob;  }
            size_t row = j >> 9, c4 = (j & 511) * 4;
            float4 v = *(const float4*)(W + row * KDIM + c4);
            __nv_bfloat16 hi[4], lo[4];
            split_bf16(v.x, hi[0], lo[0]);
            split_bf16(v.y, hi[1], lo[1]);
            split_bf16(v.z, hi[2], lo[2]);
            split_bf16(v.w, hi[3], lo[3]);
            __nv_bfloat16* dst = Wb + row * KB2 + c4;
            *(uint2*)(dst)        = *(uint2*)hi;
            *(uint2*)(dst + 2048) = *(uint2*)lo;
        } else {                                        // control state
            size_t j = k - e5;
            if (j < BSZ) {
                g_gxacc[j]  = 0.f;
                g_halted[j] = 0;
                g_rowidx[0][j] = (int)j;
            } else {
                g_rowidx[0][j] = 0;
            }
            if (j < MAXP) g_blkdone[j] = 0;
            if (j == 0) {
                g_nactive   = BSZ;
                g_done_step = (1 << 30);
                g_ponder    = MAXP;
                g_sync_cnt  = 0;
                g_sync_gen  = 0;
            }
        }
    }
}

// ---------------- ahx -> bf16x2 A-layout ----------------
__global__ void __launch_bounds__(NTHR)
k_cvt_ahx(const float* __restrict__ out)
{
    size_t i      = (size_t)blockIdx.x * blockDim.x + threadIdx.x;
    size_t stride = (size_t)gridDim.x * blockDim.x;
    for (size_t k = i; k < (size_t)BSZ * (HID / 4); k += stride) {
        size_t row = k >> 9;
        size_t c4  = (k & 511) * 4;
        float4 v = *(const float4*)(out + row * HID + c4);
        __nv_bfloat16 hi[4], lo[4];
        split_bf16(v.x, hi[0], lo[0]);
        split_bf16(v.y, hi[1], lo[1]);
        split_bf16(v.z, hi[2], lo[2]);
        split_bf16(v.w, hi[3], lo[3]);
        __nv_bfloat16* dst = g_ahxb + row * KB2 + c4;
        *(uint2*)(dst)        = *(uint2*)hi;
        *(uint2*)(dst + 2048) = *(uint2*)lo;
    }
}

// ---------------- base = xpad @ W_ih.T + b_ih + b_hh ----------------
__global__ void __launch_bounds__(NTHR)
k_base_mma(const float* __restrict__ b_ih, const float* __restrict__ b_hh)
{
    __shared__ int rowmap[128];
    float acc[4][4][4] = {};
    int m0 = blockIdx.y * 128, n0 = blockIdx.x * 128;
    mma_gemm(g_xpadb, nullptr, g_wihb, m0, n0, acc, rowmap);
    int lane = threadIdx.x & 31, warpid = threadIdx.x >> 5;
    int wm = warpid >> 2, wn = warpid & 3;
    #pragma unroll
    for (int mi = 0; mi < 4; mi++)
        #pragma unroll
        for (int e2 = 0; e2 < 2; e2++) {
            int m = m0 + wm * 64 + mi * 16 + (lane >> 2) + e2 * 8;
            #pragma unroll
            for (int ni = 0; ni < 4; ni++) {
                int n = n0 + wn * 32 + ni * 8 + (lane & 3) * 2;
                float2 w;
                w.x = acc[mi][ni][e2 * 2 + 0] + b_ih[n]     + b_hh[n];
                w.y = acc[mi][ni][e2 * 2 + 1] + b_ih[n + 1] + b_hh[n + 1];
                *(float2*)&g_base[(size_t)m * G4 + n] = w;
            }
        }
}

// ---- gates[slot] = base[row] + hx[row] @ W_hh.T (+ flag col at t==0) ----
__global__ void __launch_bounds__(NTHR)
k_gates_mma(const float* __restrict__ W_ih, int t)
{
    if (t > g_done_step) return;
    int m0 = blockIdx.y * 128;
    if (m0 >= g_nactive) return;
    int n0 = blockIdx.x * 128;
    __shared__ int rowmap[128];
    float acc[4][4][4] = {};
    mma_gemm(g_hxb, g_rowidx[t & 1], g_whhb, m0, n0, acc, rowmap);

    int lane = threadIdx.x & 31, warpid = threadIdx.x >> 5;
    int wm = warpid >> 2, wn = warpid & 3;
    #pragma unroll
    for (int mi = 0; mi < 4; mi++)
        #pragma unroll
        for (int e2 = 0; e2 < 2; e2++) {
            int ml   = wm * 64 + mi * 16 + (lane >> 2) + e2 * 8;
            int slot = m0 + ml;
            int row  = rowmap[ml];
            #pragma unroll
            for (int ni = 0; ni < 4; ni++) {
                int n = n0 + wn * 32 + ni * 8 + (lane & 3) * 2;
                float v0 = acc[mi][ni][e2 * 2 + 0] + g_base[(size_t)row * G4 + n];
                float v1 = acc[mi][ni][e2 * 2 + 1] + g_base[(size_t)row * G4 + n + 1];
                if (t == 0) {
                    v0 += W_ih[(size_t)n       * KDIM + INDIM];
                    v1 += W_ih[(size_t)(n + 1) * KDIM + INDIM];
                }
                float2 w; w.x = v0; w.y = v1;
                *(float2*)&g_gates[(size_t)slot * G4 + n] = w;
            }
        }
}

// ---- fused: LSTM cell + ponder + ahx/acx accumulation + compaction ----
// Two-half gate processing to cut register pressure (occupancy was reg-capped at 50%).
__global__ void __launch_bounds__(NTHR, 5)
k_cellrow(const float* __restrict__ W_p, const float* __restrict__ b_p,
          float* __restrict__ out, int t)
{
    if (t > g_done_step) return;
    const int slot = blockIdx.x;
    const int nact = g_nactive;

    if (slot < nact) {
        const int b = g_rowidx[t & 1][slot];
        __shared__ float red[8];
        __shared__ float s_p;

        const size_t gb = (size_t)slot * G4;
        const size_t hb = (size_t)b * HID;
        const int h0 = threadIdx.x * 8;

        float hv[8], cv[8];
        float s = 0.f;
        #pragma unroll 1
        for (int half = 0; half < 2; half++) {
            const int ho = h0 + half * 4;
            float4 gi = *(const float4*)(g_gates + gb + ho);
            float4 gf = *(const float4*)(g_gates + gb + HID + ho);
            float4 gg = *(const float4*)(g_gates + gb + 2*HID + ho);
            float4 go = *(const float4*)(g_gates + gb + 3*HID + ho);
            float4 cc = *(const float4*)(g_cx + hb + ho);
            float4 wp = *(const float4*)(W_p + ho);
            float gi_[4] = {gi.x, gi.y, gi.z, gi.w};
            float gf_[4] = {gf.x, gf.y, gf.z, gf.w};
            float gg_[4] = {gg.x, gg.y, gg.z, gg.w};
            float go_[4] = {go.x, go.y, go.z, go.w};
            float cc_[4] = {cc.x, cc.y, cc.z, cc.w};
            float wp_[4] = {wp.x, wp.y, wp.z, wp.w};
            #pragma unroll
            for (int k = 0; k < 4; k++) {
                float c  = sigf(gf_[k]) * cc_[k] + sigf(gi_[k]) * tanhf(gg_[k]);
                float hh = sigf(go_[k]) * tanhf(c);
                cv[half * 4 + k] = c;
                hv[half * 4 + k] = hh;
                s += hh * wp_[k];
            }
        }
        *(float4*)(g_cx + hb + h0)     = *(float4*)&cv[0];
        *(float4*)(g_cx + hb + h0 + 4) = *(float4*)&cv[4];
        *(float4*)(g_hx + hb + h0)     = *(float4*)&hv[0];
        *(float4*)(g_hx + hb + h0 + 4) = *(float4*)&hv[4];

        {
            __nv_bfloat16 hib[8], lob[8];
            #pragma unroll
            for (int k = 0; k < 8; k++) split_bf16(hv[k], hib[k], lob[k]);
            __nv_bfloat16* dst = g_hxb + (size_t)b * KB2 + h0;
            *(uint4*)(dst)        = *(uint4*)&hib[0];
            *(uint4*)(dst + 2048) = *(uint4*)&lob[0];
        }

        #pragma unroll
        for (int o = 16; o; o >>= 1) s += __shfl_down_sync(0xffffffffu, s, o);
        if ((threadIdx.x & 31) == 0) red[threadIdx.x >> 5] = s;
        __syncthreads();
        if (threadIdx.x == 0) {
            float tot = 0.f;
            #pragma unroll
            for (int w = 0; w < 8; w++) tot += red[w];
            float gx   = sigf(tot + b_p[0]);
            float accn = g_gxacc[b] + gx;
            bool  halt = accn > 0.99f;          // 1.0 - EPS
            float rx   = halt ? (accn - 1.0f) : 0.f;
            float p    = gx - rx;
            g_gxacc[b] = accn - rx;
            s_p        = p;
            if (halt) g_halted[b] = 1;
        }
        __syncthreads();
        const float p = s_p;
        float* ahx = out + hb;
        float* acx = out + (size_t)BSZ * HID + hb;
        float av[8], xv[8];
        *(float4*)&av[0] = *(const float4*)(ahx + h0);
        *(float4*)&av[4] = *(const float4*)(ahx + h0 + 4);
        *(float4*)&xv[0] = *(const float4*)(acx + h0);
        *(float4*)&xv[4] = *(const float4*)(acx + h0 + 4);
        #pragma unroll
        for (int k = 0; k < 8; k++) {
            av[k] += p * hv[k];
            xv[k] += p * cv[k];
        }
        *(float4*)(ahx + h0)     = *(float4*)&av[0];
        *(float4*)(ahx + h0 + 4) = *(float4*)&av[4];
        *(float4*)(acx + h0)     = *(float4*)&xv[0];
        *(float4*)(acx + h0 + 4) = *(float4*)&xv[4];
    }

    // ---- last-arriving block performs compaction for step t ----
    __shared__ int s_old;
    __threadfence();
    __syncthreads();
    if (threadIdx.x == 0) s_old = atomicAdd(&g_blkdone[t], 1);
    __syncthreads();
    if (s_old == BSZ - 1) {
        __shared__ int s_cnt;
        if (threadIdx.x == 0) s_cnt = 0;
        __syncthreads();
        const int* cur = g_rowidx[t & 1];
        int* nxt = g_rowidx[(t + 1) & 1];
        for (int s2 = threadIdx.x; s2 < nact; s2 += NTHR) {
            int row = cur[s2];
            if (!g_halted[row]) nxt[atomicAdd(&s_cnt, 1)] = row;
        }
        __syncthreads();
        int cnt = s_cnt;
        int pad_end = (cnt + 127) & ~127;
        for (int k2 = cnt + (int)threadIdx.x; k2 < pad_end; k2 += NTHR) nxt[k2] = 0;
        if (threadIdx.x == 0) {
            g_nactive = cnt;
            if (cnt == 0) {
                g_done_step = t;
                g_ponder    = t + 1;
            }
            __threadfence();
        }
    }
}

// ---------------- persistent tail: steps TSPLIT..99 in one launch ----------------
__device__ __forceinline__ void tail_gridsync(unsigned nb)
{
    __syncthreads();
    if (threadIdx.x == 0) {
        __threadfence();
        unsigned gen = g_sync_gen;
        unsigned a = atomicAdd(&g_sync_cnt, 1);
        if (a == nb - 1) {
            g_sync_cnt = 0;
            __threadfence();
            atomicAdd(&g_sync_gen, 1);
        } else {
            while (atomicAdd(&g_sync_gen, 0) == gen) __nanosleep(200);
        }
    }
    __syncthreads();
}

__global__ void __launch_bounds__(NTHR)
k_tail(const float* __restrict__ W_hh, const float* __restrict__ W_p,
       const float* __restrict__ b_p, float* __restrict__ out)
{
    const unsigned nb = gridDim.x;
    const int bid = blockIdx.x, tid = threadIdx.x;
    __shared__ float red[8];
    __shared__ float s_p;
    __shared__ int s_cnt;

    for (int t = TSPLIT; t < MAXP; t++) {
        const int nact = g_nactive;
        if (nact == 0) break;
        const int* cur = g_rowidx[t & 1];
        int* nxt = g_rowidx[(t + 1) & 1];

        for (long long w = (long long)bid * NTHR + tid; w < (long long)nact * G4;
             w += (long long)nb * NTHR) {
            int slot = (int)(w >> 13);
            int n    = (int)(w & 8191);
            int row  = cur[slot];
            const float* hx = g_hx + (size_t)row * HID;
            const float* wr = W_hh + (size_t)n * HID;
            float s = 0.f;
            for (int k = 0; k < HID; k += 4) {
                float4 a = *(const float4*)(hx + k);
                float4 b = *(const float4*)(wr + k);
                s += a.x * b.x + a.y * b.y + a.z * b.z + a.w * b.w;
            }
            g_gates[(size_t)slot * G4 + n] = s + g_base[(size_t)row * G4 + n];
        }
        tail_gridsync(nb);

        for (int slot = bid; slot < nact; slot += (int)nb) {
            const int b = cur[slot];
            const size_t gb = (size_t)slot * G4;
            const size_t hb = (size_t)b * HID;
            const int h0 = tid * 8;

            float gi[8], gf[8], gg[8], go[8], cc[8], wp[8];
            *(float4*)&gi[0] = *(const float4*)(g_gates + gb + h0);
            *(float4*)&gi[4] = *(const float4*)(g_gates + gb + h0 + 4);
            *(float4*)&gf[0] = *(const float4*)(g_gates + gb + HID + h0);
            *(float4*)&gf[4] = *(const float4*)(g_gates + gb + HID + h0 + 4);
            *(float4*)&gg[0] = *(const float4*)(g_gates + gb + 2*HID + h0);
            *(float4*)&gg[4] = *(const float4*)(g_gates + gb + 2*HID + h0 + 4);
            *(float4*)&go[0] = *(const float4*)(g_gates + gb + 3*HID + h0);
            *(float4*)&go[4] = *(const float4*)(g_gates + gb + 3*HID + h0 + 4);
            *(float4*)&cc[0] = *(const float4*)(g_cx + hb + h0);
            *(float4*)&cc[4] = *(const float4*)(g_cx + hb + h0 + 4);
            *(float4*)&wp[0] = *(const float4*)(W_p + h0);
            *(float4*)&wp[4] = *(const float4*)(W_p + h0 + 4);

            float hv[8], cv[8];
            float s = 0.f;
            #pragma unroll
            for (int k = 0; k < 8; k++) {
                float c  = sigf(gf[k]) * cc[k] + sigf(gi[k]) * tanhf(gg[k]);
                float hh = sigf(go[k]) * tanhf(c);
                cv[k] = c; hv[k] = hh;
                s += hh * wp[k];
            }
            *(float4*)(g_cx + hb + h0)     = *(float4*)&cv[0];
            *(float4*)(g_cx + hb + h0 + 4) = *(float4*)&cv[4];
            *(float4*)(g_hx + hb + h0)     = *(float4*)&hv[0];
            *(float4*)(g_hx + hb + h0 + 4) = *(float4*)&hv[4];

            #pragma unroll
            for (int o = 16; o; o >>= 1) s += __shfl_down_sync(0xffffffffu, s, o);
            if ((tid & 31) == 0) red[tid >> 5] = s;
            __syncthreads();
            if (tid == 0) {
                float tot = 0.f;
                #pragma unroll
                for (int w = 0; w < 8; w++) tot += red[w];
                float gx   = sigf(tot + b_p[0]);
                float accn = g_gxacc[b] + gx;
                bool  halt = accn > 0.99f;
                float rx   = halt ? (accn - 1.0f) : 0.f;
                float p    = gx - rx;
                g_gxacc[b] = accn - rx;
                s_p        = p;
                if (halt) g_halted[b] = 1;
            }
            __syncthreads();
            const float p = s_p;
            float* ahx = out + hb;
            float* acx = out + (size_t)BSZ * HID + hb;
            float av[8], xv[8];
            *(float4*)&av[0] = *(const float4*)(ahx + h0);
            *(float4*)&av[4] = *(const float4*)(ahx + h0 + 4);
            *(float4*)&xv[0] = *(const float4*)(acx + h0);
            *(float4*)&xv[4] = *(const float4*)(acx + h0 + 4);
            #pragma unroll
            for (int k = 0; k < 8; k++) {
                av[k] += p * hv[k];
                xv[k] += p * cv[k];
            }
            *(float4*)(ahx + h0)     = *(float4*)&av[0];
            *(float4*)(ahx + h0 + 4) = *(float4*)&av[4];
            *(float4*)(acx + h0)     = *(float4*)&xv[0];
            *(float4*)(acx + h0 + 4) = *(float4*)&xv[4];
            __syncthreads();
        }
        tail_gridsync(nb);

        if (bid == 0) {
            if (tid == 0) s_cnt = 0;
            __syncthreads();
            for (int s2 = tid; s2 < nact; s2 += NTHR) {
                int row = cur[s2];
                if (!g_halted[row]) nxt[atomicAdd(&s_cnt, 1)] = row;
            }
            __syncthreads();
            int cnt = s_cnt;
            int pad_end = (cnt + 127) & ~127;
            for (int k2 = cnt + tid; k2 < pad_end; k2 += NTHR) nxt[k2] = 0;
            if (tid == 0) {
                g_nactive = cnt;
                if (cnt == 0) g_ponder = t + 1;
                __threadfence();
            }
        }
        tail_gridsync(nb);
    }
}

// ---------------- final: aout = ahx @ W_o.T + (sum p) * b_o ----------------
__global__ void __launch_bounds__(NTHR)
k_aout_mma(const float* __restrict__ b_o, float* __restrict__ out)
{
    __shared__ int rowmap[128];
    float acc[4][4][4] = {};
    int m0 = blockIdx.y * 128, n0 = blockIdx.x * 128;
    mma_gemm(g_ahxb, nullptr, g_wob, m0, n0, acc, rowmap);
    float* aout = out + (size_t)2 * BSZ * HID;
    int lane = threadIdx.x & 31, warpid = threadIdx.x >> 5;
    int wm = warpid >> 2, wn = warpid & 3;
    #pragma unroll
    for (int mi = 0; mi < 4; mi++)
        #pragma unroll
        for (int e2 = 0; e2 < 2; e2++) {
            int m = m0 + wm * 64 + mi * 16 + (lane >> 2) + e2 * 8;
            float sp = g_gxacc[m];
            #pragma unroll
            for (int ni = 0; ni < 4; ni++) {
                int n = n0 + wn * 32 + ni * 8 + (lane & 3) * 2;
                float2 w;
                w.x = acc[mi][ni][e2 * 2 + 0] + sp * b_o[n];
                w.y = acc[mi][ni][e2 * 2 + 1] + sp * b_o[n + 1];
                *(float2*)&aout[(size_t)m * OUTD + n] = w;
            }
        }
}

// ---------------- finalize ----------------
__global__ void k_fin(float* __restrict__ out, int out_size)
{
    if (blockIdx.x == 0 && threadIdx.x == 0)
        out[out_size - 1] = (float)g_ponder;
}

// ---------------- host ----------------
extern "C" void kernel_launch(void* const* d_in, const int* in_sizes, int n_in,
                              void* d_out, int out_size)
{
    const float* x    = (const float*)d_in[0];
    const float* hx0  = (const float*)d_in[1];
    const float* cx0  = (const float*)d_in[2];
    const float* W_ih = (const float*)d_in[3];
    const float* b_ih = (const float*)d_in[4];
    const float* W_hh = (const float*)d_in[5];
    const float* b_hh = (const float*)d_in[6];
    const float* W_p  = (const float*)d_in[7];
    const float* b_p  = (const float*)d_in[8];
    const float* W_o  = (const float*)d_in[9];
    const float* b_o  = (const float*)d_in[10];
    float* out = (float*)d_out;

    k_setup<<<4096, NTHR>>>(x, hx0, cx0, W_ih, W_hh, W_o, out);

    dim3 gbig(G4 / 128, BSZ / 128);     // 64 x 16
    dim3 gout(OUTD / 128, BSZ / 128);   // 16 x 16
    k_base_mma<<<gbig, NTHR>>>(b_ih, b_hh);

    for (int t = 0; t < TSPLIT; t++) {
        k_gates_mma<<<gbig, NTHR>>>(W_ih, t);
        k_cellrow<<<BSZ, NTHR>>>(W_p, b_p, out, t);
    }
    k_tail<<<148, NTHR>>>(W_hh, W_p, b_p, out);

    k_cvt_ahx<<<2048, NTHR>>>(out);
    k_aout_mma<<<gout, NTHR>>>(b_o, out);
    k_fin<<<1, 1>>>(out, out_size);
}

// round 16
// speedup vs baseline: 1.0611x; 1.0611x over previous
#include <cuda_runtime.h>
#include <cuda_bf16.h>
#include <math.h>

#define BSZ   2048
#define HID   2048
#define G4    8192
#define OUTD  2048
#define INDIM 2047
#define KDIM  2048
#define KB3   6144          // 3 * KDIM (bf16x3 K-extension)
#define MAXP  100
#define TSPLIT 6
#define NTHR  256
#define LDA   40            // smem row stride in elements (80B, conflict-free)
#define KCH   32
#define NCHUNK (KB3 / KCH)  // 192

// ---------------- device scratch ----------------
__device__ __align__(16) __nv_bfloat16 g_xpadb[(size_t)BSZ * KB3];  // A-side (hi,hi,lo)
__device__ __align__(16) __nv_bfloat16 g_hxb  [(size_t)BSZ * KB3];  // A-side
__device__ __align__(16) __nv_bfloat16 g_ahxb [(size_t)BSZ * KB3];  // A-side
__device__ __align__(16) __nv_bfloat16 g_wihb [(size_t)G4  * KB3];  // B-side (hi,lo,hi)
__device__ __align__(16) __nv_bfloat16 g_whhb [(size_t)G4  * KB3];  // B-side
__device__ __align__(16) __nv_bfloat16 g_wob  [(size_t)OUTD* KB3];  // B-side
__device__ __align__(16) float g_base [(size_t)BSZ * G4];
__device__ __align__(16) float g_gates[(size_t)BSZ * G4];
__device__ __align__(16) float g_hx   [(size_t)BSZ * HID];
__device__ __align__(16) float g_cx   [(size_t)BSZ * HID];
__device__ float g_gxacc[BSZ];
__device__ int   g_halted[BSZ];
__device__ int   g_rowidx[2][BSZ + 128];
__device__ int   g_blkdone[MAXP];
__device__ int   g_nactive;
__device__ int   g_done_step;
__device__ int   g_ponder;
__device__ unsigned g_sync_cnt;
__device__ unsigned g_sync_gen;

__device__ __forceinline__ float sigf(float x) { return 1.0f / (1.0f + expf(-x)); }

__device__ __forceinline__ void split_bf16(float v, __nv_bfloat16& hi, __nv_bfloat16& lo)
{
    hi = __float2bfloat16(v);
    lo = __float2bfloat16(v - __bfloat162float(hi));
}

// ---------------- PTX helpers ----------------
__device__ __forceinline__ unsigned su32(const void* p)
{
    return (unsigned)__cvta_generic_to_shared(p);
}
__device__ __forceinline__ void cp16(unsigned dst, const void* src)
{
    asm volatile("cp.async.cg.shared.global [%0], [%1], 16;" :: "r"(dst), "l"(src));
}
__device__ __forceinline__ void cp_commit()
{
    asm volatile("cp.async.commit_group;" ::: "memory");
}
template <int N> __device__ __forceinline__ void cp_wait()
{
    asm volatile("cp.async.wait_group %0;" :: "n"(N) : "memory");
}
__device__ __forceinline__ void ldsm4(unsigned& r0, unsigned& r1, unsigned& r2, unsigned& r3,
                                      unsigned addr)
{
    asm volatile("ldmatrix.sync.aligned.m8n8.x4.shared.b16 {%0,%1,%2,%3}, [%4];"
                 : "=r"(r0), "=r"(r1), "=r"(r2), "=r"(r3) : "r"(addr));
}
__device__ __forceinline__ void mma16816(float& d0, float& d1, float& d2, float& d3,
                                         unsigned a0, unsigned a1, unsigned a2, unsigned a3,
                                         unsigned b0, unsigned b1)
{
    asm volatile("mma.sync.aligned.m16n8k16.row.col.f32.bf16.bf16.f32 "
                 "{%0,%1,%2,%3}, {%4,%5,%6,%7}, {%8,%9}, {%0,%1,%2,%3};"
                 : "+f"(d0), "+f"(d1), "+f"(d2), "+f"(d3)
                 : "r"(a0), "r"(a1), "r"(a2), "r"(a3), "r"(b0), "r"(b1));
}

// ------------- 128x128 bf16 MMA GEMM tile (R9/R14 config — at mma.sync ceiling) -------------
// 256 threads = 8 warps (2x4). Warp tile 64x32. cp.async double-buffered smem.
__device__ __forceinline__ void mma_gemm(
    const __nv_bfloat16* __restrict__ A, const int* __restrict__ rows,
    const __nv_bfloat16* __restrict__ B,
    int m0, int n0, float (&acc)[4][4][4], int* rowmap)
{
    __shared__ __align__(16) __nv_bfloat16 As[2][128 * LDA];
    __shared__ __align__(16) __nv_bfloat16 Bs[2][128 * LDA];
    const int tid = threadIdx.x;

    if (rows) {
        if (tid < 128) rowmap[tid] = rows[m0 + tid];
        __syncthreads();
    }

    const unsigned suA[2] = { su32(&As[0][0]), su32(&As[1][0]) };
    const unsigned suB[2] = { su32(&Bs[0][0]), su32(&Bs[1][0]) };
    const __nv_bfloat16* srcA[2];
    const __nv_bfloat16* srcB[2];
    unsigned offA[2], offB[2];
    #pragma unroll
    for (int u = 0; u < 2; u++) {
        int idx = tid * 2 + u;          // 0..511
        int row = idx >> 2, sub = idx & 3;
        int ar  = rows ? rowmap[row] : (m0 + row);
        srcA[u] = A + (size_t)ar * KB3 + sub * 8;
        srcB[u] = B + (size_t)(n0 + row) * KB3 + sub * 8;
        offA[u] = (unsigned)(row * (LDA * 2) + sub * 16);   // bytes
        offB[u] = offA[u];
    }

    const int lane = tid & 31, warpid = tid >> 5;
    const int wm = warpid >> 2, wn = warpid & 3;
    const int a_r = lane & 15;
    const int a_c = (lane >> 4) << 3;
    const int b_r = ((lane >> 4) << 3) + (lane & 7);
    const int b_c = ((lane >> 3) & 1) << 3;

    #pragma unroll
    for (int u = 0; u < 2; u++) cp16(suA[0] + offA[u], srcA[u]);
    #pragma unroll
    for (int u = 0; u < 2; u++) cp16(suB[0] + offB[u], srcB[u]);
    cp_commit();

    for (int ch = 0; ch < NCHUNK; ch++) {
        const int buf = ch & 1;
        if (ch + 1 < NCHUNK) {
            const int kb2 = (ch + 1) * KCH;
            const int nb = buf ^ 1;
            #pragma unroll
            for (int u = 0; u < 2; u++) cp16(suA[nb] + offA[u], srcA[u] + kb2);
            #pragma unroll
            for (int u = 0; u < 2; u++) cp16(suB[nb] + offB[u], srcB[u] + kb2);
            cp_commit();
            cp_wait<1>();
        } else {
            cp_wait<0>();
        }
        __syncthreads();

        #pragma unroll
        for (int kh = 0; kh < 2; kh++) {
            const int kb = kh * 16;
            unsigned af[4][4], bq[2][4];
            #pragma unroll
            for (int mi = 0; mi < 4; mi++) {
                int r = wm * 64 + mi * 16 + a_r;
                ldsm4(af[mi][0], af[mi][1], af[mi][2], af[mi][3],
                      suA[buf] + (unsigned)(r * (LDA * 2) + (kb + a_c) * 2));
            }
            #pragma unroll
            for (int np = 0; np < 2; np++) {
                int r = wn * 32 + np * 16 + b_r;
                ldsm4(bq[np][0], bq[np][1], bq[np][2], bq[np][3],
                      suB[buf] + (unsigned)(r * (LDA * 2) + (kb + b_c) * 2));
            }
            #pragma unroll
            for (int mi = 0; mi < 4; mi++) {
                #pragma unroll
                for (int np = 0; np < 2; np++) {
                    mma16816(acc[mi][np*2][0], acc[mi][np*2][1], acc[mi][np*2][2], acc[mi][np*2][3],
                             af[mi][0], af[mi][1], af[mi][2], af[mi][3],
                             bq[np][0], bq[np][1]);
                    mma16816(acc[mi][np*2+1][0], acc[mi][np*2+1][1], acc[mi][np*2+1][2], acc[mi][np*2+1][3],
                             af[mi][0], af[mi][1], af[mi][2], af[mi][3],
                             bq[np][2], bq[np][3]);
                }
            }
        }
        __syncthreads();
    }
}

// ---------------- fused setup: all init/pack/convert work in ONE kernel ----------------
__global__ void __launch_bounds__(NTHR)
k_setup(const float* __restrict__ x,
        const float* __restrict__ hx0, const float* __restrict__ cx0,
        const float* __restrict__ W_ih, const float* __restrict__ W_hh,
        const float* __restrict__ W_o, float* __restrict__ out)
{
    const size_t nA = (size_t)2 * BSZ * HID / 4;
    const size_t nB = (size_t)BSZ * HID / 4;
    const size_t nC = (size_t)BSZ * (KDIM / 4);
    const size_t nD = (size_t)G4  * (KDIM / 4);
    const size_t nE = (size_t)G4  * (KDIM / 4);
    const size_t nF = (size_t)OUTD* (KDIM / 4);
    const size_t nG = BSZ + 128;
    const size_t e0 = nA, e1 = e0 + nB, e2 = e1 + nC, e3 = e2 + nD,
                 e4 = e3 + nE, e5 = e4 + nF, e6 = e5 + nG;

    size_t i      = (size_t)blockIdx.x * blockDim.x + threadIdx.x;
    size_t stride = (size_t)gridDim.x * blockDim.x;
    for (size_t k = i; k < e6; k += stride) {
        if (k < e0) {
            float4 z = {0.f, 0.f, 0.f, 0.f};
            *(float4*)(out + k * 4) = z;
        } else if (k < e1) {                            // hx/cx + hxb
            size_t j = k - e0;
            size_t row = j >> 9, c4 = (j & 511) * 4;
            size_t off = row * HID + c4;
            float4 h = *(const float4*)(hx0 + off);
            float4 c = *(const float4*)(cx0 + off);
            *(float4*)(g_hx + off) = h;
            *(float4*)(g_cx + off) = c;
            __nv_bfloat16 hi[4], lo[4];
            split_bf16(h.x, hi[0], lo[0]);
            split_bf16(h.y, hi[1], lo[1]);
            split_bf16(h.z, hi[2], lo[2]);
            split_bf16(h.w, hi[3], lo[3]);
            __nv_bfloat16* dst = g_hxb + row * KB3 + c4;
            *(uint2*)(dst)        = *(uint2*)hi;
            *(uint2*)(dst + 2048) = *(uint2*)hi;
            *(uint2*)(dst + 4096) = *(uint2*)lo;
        } else if (k < e2) {                            // xpad
            size_t j = k - e1;
            size_t row = j >> 9, c0 = (j & 511) * 4;
            const float* xr = x + row * INDIM;
            __nv_bfloat16 hi[4], lo[4];
            #pragma unroll
            for (int u = 0; u < 4; u++) {
                size_t col = c0 + u;
                float v = (col < INDIM) ? xr[col] : 0.f;
                split_bf16(v, hi[u], lo[u]);
            }
            __nv_bfloat16* dst = g_xpadb + row * KB3 + c0;
            *(uint2*)(dst)        = *(uint2*)hi;
            *(uint2*)(dst + 2048) = *(uint2*)hi;
            *(uint2*)(dst + 4096) = *(uint2*)lo;
        } else if (k < e5) {                            // weight conversions
            size_t j;
            const float* W;
            __nv_bfloat16* Wb;
            if (k < e3)      { j = k - e2; W = W_ih; Wb = g_wihb; }
            else if (k < e4) { j = k - e3; W = W_hh; Wb = g_whhb; }
            else             { j = k - e4; W = W_o;  Wb = g_wob;  }
            size_t row = j >> 9, c4 = (j & 511) * 4;
            float4 v = *(const float4*)(W + row * KDIM + c4);
            __nv_bfloat16 hi[4], lo[4];
            split_bf16(v.x, hi[0], lo[0]);
            split_bf16(v.y, hi[1], lo[1]);
            split_bf16(v.z, hi[2], lo[2]);
            split_bf16(v.w, hi[3], lo[3]);
            __nv_bfloat16* dst = Wb + row * KB3 + c4;
            *(uint2*)(dst)        = *(uint2*)hi;
            *(uint2*)(dst + 2048) = *(uint2*)lo;
            *(uint2*)(dst + 4096) = *(uint2*)hi;
        } else {                                        // control state
            size_t j = k - e5;
            if (j < BSZ) {
                g_gxacc[j]  = 0.f;
                g_halted[j] = 0;
                g_rowidx[0][j] = (int)j;
            } else {
                g_rowidx[0][j] = 0;
            }
            if (j < MAXP) g_blkdone[j] = 0;
            if (j == 0) {
                g_nactive   = BSZ;
                g_done_step = (1 << 30);
                g_ponder    = MAXP;
                g_sync_cnt  = 0;
                g_sync_gen  = 0;
            }
        }
    }
}

// ---------------- ahx -> bf16x3 A-layout, vectorized ----------------
__global__ void __launch_bounds__(NTHR)
k_cvt_ahx(const float* __restrict__ out)
{
    size_t i      = (size_t)blockIdx.x * blockDim.x + threadIdx.x;
    size_t stride = (size_t)gridDim.x * blockDim.x;
    for (size_t k = i; k < (size_t)BSZ * (HID / 4); k += stride) {
        size_t row = k >> 9;
        size_t c4  = (k & 511) * 4;
        float4 v = *(const float4*)(out + row * HID + c4);
        __nv_bfloat16 hi[4], lo[4];
        split_bf16(v.x, hi[0], lo[0]);
        split_bf16(v.y, hi[1], lo[1]);
        split_bf16(v.z, hi[2], lo[2]);
        split_bf16(v.w, hi[3], lo[3]);
        __nv_bfloat16* dst = g_ahxb + row * KB3 + c4;
        *(uint2*)(dst)        = *(uint2*)hi;
        *(uint2*)(dst + 2048) = *(uint2*)hi;
        *(uint2*)(dst + 4096) = *(uint2*)lo;
    }
}

// ---------------- base = xpad @ W_ih.T + b_ih + b_hh ----------------
__global__ void __launch_bounds__(NTHR)
k_base_mma(const float* __restrict__ b_ih, const float* __restrict__ b_hh)
{
    __shared__ int rowmap[128];
    float acc[4][4][4] = {};
    int m0 = blockIdx.y * 128, n0 = blockIdx.x * 128;
    mma_gemm(g_xpadb, nullptr, g_wihb, m0, n0, acc, rowmap);
    int lane = threadIdx.x & 31, warpid = threadIdx.x >> 5;
    int wm = warpid >> 2, wn = warpid & 3;
    #pragma unroll
    for (int mi = 0; mi < 4; mi++)
        #pragma unroll
        for (int e2 = 0; e2 < 2; e2++) {
            int m = m0 + wm * 64 + mi * 16 + (lane >> 2) + e2 * 8;
            #pragma unroll
            for (int ni = 0; ni < 4; ni++) {
                int n = n0 + wn * 32 + ni * 8 + (lane & 3) * 2;
                float2 w;
                w.x = acc[mi][ni][e2 * 2 + 0] + b_ih[n]     + b_hh[n];
                w.y = acc[mi][ni][e2 * 2 + 1] + b_ih[n + 1] + b_hh[n + 1];
                *(float2*)&g_base[(size_t)m * G4 + n] = w;
            }
        }
}

// ---- gates[slot] = base[row] + hx[row] @ W_hh.T (+ flag col at t==0) ----
__global__ void __launch_bounds__(NTHR)
k_gates_mma(const float* __restrict__ W_ih, int t)
{
    if (t > g_done_step) return;
    int m0 = blockIdx.y * 128;
    if (m0 >= g_nactive) return;
    int n0 = blockIdx.x * 128;
    __shared__ int rowmap[128];
    float acc[4][4][4] = {};
    mma_gemm(g_hxb, g_rowidx[t & 1], g_whhb, m0, n0, acc, rowmap);

    int lane = threadIdx.x & 31, warpid = threadIdx.x >> 5;
    int wm = warpid >> 2, wn = warpid & 3;
    #pragma unroll
    for (int mi = 0; mi < 4; mi++)
        #pragma unroll
        for (int e2 = 0; e2 < 2; e2++) {
            int ml   = wm * 64 + mi * 16 + (lane >> 2) + e2 * 8;
            int slot = m0 + ml;
            int row  = rowmap[ml];
            #pragma unroll
            for (int ni = 0; ni < 4; ni++) {
                int n = n0 + wn * 32 + ni * 8 + (lane & 3) * 2;
                float v0 = acc[mi][ni][e2 * 2 + 0] + g_base[(size_t)row * G4 + n];
                float v1 = acc[mi][ni][e2 * 2 + 1] + g_base[(size_t)row * G4 + n + 1];
                if (t == 0) {
                    v0 += W_ih[(size_t)n       * KDIM + INDIM];
                    v1 += W_ih[(size_t)(n + 1) * KDIM + INDIM];
                }
                float2 w; w.x = v0; w.y = v1;
                *(float2*)&g_gates[(size_t)slot * G4 + n] = w;
            }
        }
}

// ---- fused: LSTM cell + ponder + ahx/acx accumulation + compaction (R14 version) ----
__global__ void __launch_bounds__(NTHR)
k_cellrow(const float* __restrict__ W_p, const float* __restrict__ b_p,
          float* __restrict__ out, int t)
{
    if (t > g_done_step) return;
    const int slot = blockIdx.x;
    const int nact = g_nactive;

    if (slot < nact) {
        const int b = g_rowidx[t & 1][slot];
        __shared__ float red[8];
        __shared__ float s_p;

        const size_t gb = (size_t)slot * G4;
        const size_t hb = (size_t)b * HID;
        const int h0 = threadIdx.x * 8;

        float gi[8], gf[8], gg[8], go[8], cc[8], wp[8];
        *(float4*)&gi[0] = *(const float4*)(g_gates + gb + h0);
        *(float4*)&gi[4] = *(const float4*)(g_gates + gb + h0 + 4);
        *(float4*)&gf[0] = *(const float4*)(g_gates + gb + HID + h0);
        *(float4*)&gf[4] = *(const float4*)(g_gates + gb + HID + h0 + 4);
        *(float4*)&gg[0] = *(const float4*)(g_gates + gb + 2*HID + h0);
        *(float4*)&gg[4] = *(const float4*)(g_gates + gb + 2*HID + h0 + 4);
        *(float4*)&go[0] = *(const float4*)(g_gates + gb + 3*HID + h0);
        *(float4*)&go[4] = *(const float4*)(g_gates + gb + 3*HID + h0 + 4);
        *(float4*)&cc[0] = *(const float4*)(g_cx + hb + h0);
        *(float4*)&cc[4] = *(const float4*)(g_cx + hb + h0 + 4);
        *(float4*)&wp[0] = *(const float4*)(W_p + h0);
        *(float4*)&wp[4] = *(const float4*)(W_p + h0 + 4);

        float hv[8], cv[8];
        float s = 0.f;
        #pragma unroll
        for (int k = 0; k < 8; k++) {
            float c  = sigf(gf[k]) * cc[k] + sigf(gi[k]) * tanhf(gg[k]);
            float hh = sigf(go[k]) * tanhf(c);
            cv[k] = c; hv[k] = hh;
            s += hh * wp[k];
        }
        *(float4*)(g_cx + hb + h0)     = *(float4*)&cv[0];
        *(float4*)(g_cx + hb + h0 + 4) = *(float4*)&cv[4];
        *(float4*)(g_hx + hb + h0)     = *(float4*)&hv[0];
        *(float4*)(g_hx + hb + h0 + 4) = *(float4*)&hv[4];

        {
            __nv_bfloat16 hib[8], lob[8];
            #pragma unroll
            for (int k = 0; k < 8; k++) split_bf16(hv[k], hib[k], lob[k]);
            __nv_bfloat16* dst = g_hxb + (size_t)b * KB3 + h0;
            *(uint4*)(dst)        = *(uint4*)&hib[0];
            *(uint4*)(dst + 2048) = *(uint4*)&hib[0];
            *(uint4*)(dst + 4096) = *(uint4*)&lob[0];
        }

        #pragma unroll
        for (int o = 16; o; o >>= 1) s += __shfl_down_sync(0xffffffffu, s, o);
        if ((threadIdx.x & 31) == 0) red[threadIdx.x >> 5] = s;
        __syncthreads();
        if (threadIdx.x == 0) {
            float tot = 0.f;
            #pragma unroll
            for (int w = 0; w < 8; w++) tot += red[w];
            float gx   = sigf(tot + b_p[0]);
            float accn = g_gxacc[b] + gx;
            bool  halt = accn > 0.99f;          // 1.0 - EPS
            float rx   = halt ? (accn - 1.0f) : 0.f;
            float p    = gx - rx;
            g_gxacc[b] = accn - rx;
            s_p        = p;
            if (halt) g_halted[b] = 1;
        }
        __syncthreads();
        const float p = s_p;
        float* ahx = out + hb;
        float* acx = out + (size_t)BSZ * HID + hb;
        float av[8], xv[8];
        *(float4*)&av[0] = *(const float4*)(ahx + h0);
        *(float4*)&av[4] = *(const float4*)(ahx + h0 + 4);
        *(float4*)&xv[0] = *(const float4*)(acx + h0);
        *(float4*)&xv[4] = *(const float4*)(acx + h0 + 4);
        #pragma unroll
        for (int k = 0; k < 8; k++) {
            av[k] += p * hv[k];
            xv[k] += p * cv[k];
        }
        *(float4*)(ahx + h0)     = *(float4*)&av[0];
        *(float4*)(ahx + h0 + 4) = *(float4*)&av[4];
        *(float4*)(acx + h0)     = *(float4*)&xv[0];
        *(float4*)(acx + h0 + 4) = *(float4*)&xv[4];
    }

    // ---- last-arriving block performs compaction for step t ----
    __shared__ int s_old;
    __threadfence();
    __syncthreads();
    if (threadIdx.x == 0) s_old = atomicAdd(&g_blkdone[t], 1);
    __syncthreads();
    if (s_old == BSZ - 1) {
        __shared__ int s_cnt;
        if (threadIdx.x == 0) s_cnt = 0;
        __syncthreads();
        const int* cur = g_rowidx[t & 1];
        int* nxt = g_rowidx[(t + 1) & 1];
        for (int s2 = threadIdx.x; s2 < nact; s2 += NTHR) {
            int row = cur[s2];
            if (!g_halted[row]) nxt[atomicAdd(&s_cnt, 1)] = row;
        }
        __syncthreads();
        int cnt = s_cnt;
        int pad_end = (cnt + 127) & ~127;
        for (int k2 = cnt + (int)threadIdx.x; k2 < pad_end; k2 += NTHR) nxt[k2] = 0;
        if (threadIdx.x == 0) {
            g_nactive = cnt;
            if (cnt == 0) {
                g_done_step = t;
                g_ponder    = t + 1;
            }
            __threadfence();
        }
    }
}

// ---------------- persistent tail: steps TSPLIT..99 in one launch ----------------
__device__ __forceinline__ void tail_gridsync(unsigned nb)
{
    __syncthreads();
    if (threadIdx.x == 0) {
        __threadfence();
        unsigned gen = g_sync_gen;
        unsigned a = atomicAdd(&g_sync_cnt, 1);
        if (a == nb - 1) {
            g_sync_cnt = 0;
            __threadfence();
            atomicAdd(&g_sync_gen, 1);
        } else {
            while (atomicAdd(&g_sync_gen, 0) == gen) __nanosleep(200);
        }
    }
    __syncthreads();
}

__global__ void __launch_bounds__(NTHR)
k_tail(const float* __restrict__ W_hh, const float* __restrict__ W_p,
       const float* __restrict__ b_p, float* __restrict__ out)
{
    const unsigned nb = gridDim.x;
    const int bid = blockIdx.x, tid = threadIdx.x;
    __shared__ float red[8];
    __shared__ float s_p;
    __shared__ int s_cnt;

    for (int t = TSPLIT; t < MAXP; t++) {
        const int nact = g_nactive;
        if (nact == 0) break;
        const int* cur = g_rowidx[t & 1];
        int* nxt = g_rowidx[(t + 1) & 1];

        for (long long w = (long long)bid * NTHR + tid; w < (long long)nact * G4;
             w += (long long)nb * NTHR) {
            int slot = (int)(w >> 13);
            int n    = (int)(w & 8191);
            int row  = cur[slot];
            const float* hx = g_hx + (size_t)row * HID;
            const float* wr = W_hh + (size_t)n * HID;
            float s = 0.f;
            for (int k = 0; k < HID; k += 4) {
                float4 a = *(const float4*)(hx + k);
                float4 b = *(const float4*)(wr + k);
                s += a.x * b.x + a.y * b.y + a.z * b.z + a.w * b.w;
            }
            g_gates[(size_t)slot * G4 + n] = s + g_base[(size_t)row * G4 + n];
        }
        tail_gridsync(nb);

        for (int slot = bid; slot < nact; slot += (int)nb) {
            const int b = cur[slot];
            const size_t gb = (size_t)slot * G4;
            const size_t hb = (size_t)b * HID;
            const int h0 = tid * 8;

            float gi[8], gf[8], gg[8], go[8], cc[8], wp[8];
            *(float4*)&gi[0] = *(const float4*)(g_gates + gb + h0);
            *(float4*)&gi[4] = *(const float4*)(g_gates + gb + h0 + 4);
            *(float4*)&gf[0] = *(const float4*)(g_gates + gb + HID + h0);
            *(float4*)&gf[4] = *(const float4*)(g_gates + gb + HID + h0 + 4);
            *(float4*)&gg[0] = *(const float4*)(g_gates + gb + 2*HID + h0);
            *(float4*)&gg[4] = *(const float4*)(g_gates + gb + 2*HID + h0 + 4);
            *(float4*)&go[0] = *(const float4*)(g_gates + gb + 3*HID + h0);
            *(float4*)&go[4] = *(const float4*)(g_gates + gb + 3*HID + h0 + 4);
            *(float4*)&cc[0] = *(const float4*)(g_cx + hb + h0);
            *(float4*)&cc[4] = *(const float4*)(g_cx + hb + h0 + 4);
            *(float4*)&wp[0] = *(const float4*)(W_p + h0);
            *(float4*)&wp[4] = *(const float4*)(W_p + h0 + 4);

            float hv[8], cv[8];
            float s = 0.f;
            #pragma unroll
            for (int k = 0; k < 8; k++) {
                float c  = sigf(gf[k]) * cc[k] + sigf(gi[k]) * tanhf(gg[k]);
                float hh = sigf(go[k]) * tanhf(c);
                cv[k] = c; hv[k] = hh;
                s += hh * wp[k];
            }
            *(float4*)(g_cx + hb + h0)     = *(float4*)&cv[0];
            *(float4*)(g_cx + hb + h0 + 4) = *(float4*)&cv[4];
            *(float4*)(g_hx + hb + h0)     = *(float4*)&hv[0];
            *(float4*)(g_hx + hb + h0 + 4) = *(float4*)&hv[4];

            {
                __nv_bfloat16 hib[8], lob[8];
                #pragma unroll
                for (int k = 0; k < 8; k++) split_bf16(hv[k], hib[k], lob[k]);
                __nv_bfloat16* dst = g_hxb + (size_t)b * KB3 + h0;
                *(uint4*)(dst)        = *(uint4*)&hib[0];
                *(uint4*)(dst + 2048) = *(uint4*)&hib[0];
                *(uint4*)(dst + 4096) = *(uint4*)&lob[0];
            }

            #pragma unroll
            for (int o = 16; o; o >>= 1) s += __shfl_down_sync(0xffffffffu, s, o);
            if ((tid & 31) == 0) red[tid >> 5] = s;
            __syncthreads();
            if (tid == 0) {
                float tot = 0.f;
                #pragma unroll
                for (int w = 0; w < 8; w++) tot += red[w];
                float gx   = sigf(tot + b_p[0]);
                float accn = g_gxacc[b] + gx;
                bool  halt = accn > 0.99f;
                float rx   = halt ? (accn - 1.0f) : 0.f;
                float p    = gx - rx;
                g_gxacc[b] = accn - rx;
                s_p        = p;
                if (halt) g_halted[b] = 1;
            }
            __syncthreads();
            const float p = s_p;
            float* ahx = out + hb;
            float* acx = out + (size_t)BSZ * HID + hb;
            float av[8], xv[8];
            *(float4*)&av[0] = *(const float4*)(ahx + h0);
            *(float4*)&av[4] = *(const float4*)(ahx + h0 + 4);
            *(float4*)&xv[0] = *(const float4*)(acx + h0);
            *(float4*)&xv[4] = *(const float4*)(acx + h0 + 4);
            #pragma unroll
            for (int k = 0; k < 8; k++) {
                av[k] += p * hv[k];
                xv[k] += p * cv[k];
            }
            *(float4*)(ahx + h0)     = *(float4*)&av[0];
            *(float4*)(ahx + h0 + 4) = *(float4*)&av[4];
            *(float4*)(acx + h0)     = *(float4*)&xv[0];
            *(float4*)(acx + h0 + 4) = *(float4*)&xv[4];
            __syncthreads();
        }
        tail_gridsync(nb);

        if (bid == 0) {
            if (tid == 0) s_cnt = 0;
            __syncthreads();
            for (int s2 = tid; s2 < nact; s2 += NTHR) {
                int row = cur[s2];
                if (!g_halted[row]) nxt[atomicAdd(&s_cnt, 1)] = row;
            }
            __syncthreads();
            int cnt = s_cnt;
            int pad_end = (cnt + 127) & ~127;
            for (int k2 = cnt + tid; k2 < pad_end; k2 += NTHR) nxt[k2] = 0;
            if (tid == 0) {
                g_nactive = cnt;
                if (cnt == 0) g_ponder = t + 1;
                __threadfence();
            }
        }
        tail_gridsync(nb);
    }
}

// ---------------- final: aout = ahx @ W_o.T + (sum p) * b_o  (+ ponder write) ----------------
__global__ void __launch_bounds__(NTHR)
k_aout_mma(const float* __restrict__ b_o, float* __restrict__ out, int out_size)
{
    __shared__ int rowmap[128];
    float acc[4][4][4] = {};
    int m0 = blockIdx.y * 128, n0 = blockIdx.x * 128;
    mma_gemm(g_ahxb, nullptr, g_wob, m0, n0, acc, rowmap);
    float* aout = out + (size_t)2 * BSZ * HID;
    int lane = threadIdx.x & 31, warpid = threadIdx.x >> 5;
    int wm = warpid >> 2, wn = warpid & 3;
    #pragma unroll
    for (int mi = 0; mi < 4; mi++)
        #pragma unroll
        for (int e2 = 0; e2 < 2; e2++) {
            int m = m0 + wm * 64 + mi * 16 + (lane >> 2) + e2 * 8;
            float sp = g_gxacc[m];
            #pragma unroll
            for (int ni = 0; ni < 4; ni++) {
                int n = n0 + wn * 32 + ni * 8 + (lane & 3) * 2;
                float2 w;
                w.x = acc[mi][ni][e2 * 2 + 0] + sp * b_o[n];
                w.y = acc[mi][ni][e2 * 2 + 1] + sp * b_o[n + 1];
                *(float2*)&aout[(size_t)m * OUTD + n] = w;
            }
        }
    // ponder count (out_size-1 lies beyond the aout region; no conflict)
    if (blockIdx.x == 0 && blockIdx.y == 0 && threadIdx.x == 0)
        out[out_size - 1] = (float)g_ponder;
}

// ---------------- host ----------------
extern "C" void kernel_launch(void* const* d_in, const int* in_sizes, int n_in,
                              void* d_out, int out_size)
{
    const float* x    = (const float*)d_in[0];
    const float* hx0  = (const float*)d_in[1];
    const float* cx0  = (const float*)d_in[2];
    const float* W_ih = (const float*)d_in[3];
    const float* b_ih = (const float*)d_in[4];
    const float* W_hh = (const float*)d_in[5];
    const float* b_hh = (const float*)d_in[6];
    const float* W_p  = (const float*)d_in[7];
    const float* b_p  = (const float*)d_in[8];
    const float* W_o  = (const float*)d_in[9];
    const float* b_o  = (const float*)d_in[10];
    float* out = (float*)d_out;

    k_setup<<<4096, NTHR>>>(x, hx0, cx0, W_ih, W_hh, W_o, out);

    dim3 gbig(G4 / 128, BSZ / 128);     // 64 x 16
    dim3 gout(OUTD / 128, BSZ / 128);   // 16 x 16
    k_base_mma<<<gbig, NTHR>>>(b_ih, b_hh);

    for (int t = 0; t < TSPLIT; t++) {
        k_gates_mma<<<gbig, NTHR>>>(W_ih, t);
        k_cellrow<<<BSZ, NTHR>>>(W_p, b_p, out, t);
    }
    k_tail<<<148, NTHR>>>(W_hh, W_p, b_p, out);

    k_cvt_ahx<<<2048, NTHR>>>(out);
    k_aout_mma<<<gout, NTHR>>>(b_o, out, out_size);
}